// round 15
// baseline (speedup 1.0000x reference)
#include <cuda_runtime.h>
#include <cstdint>
#include <cstddef>

#define HID     64
#define DIMH    128
#define DIMU    256
#define CROWS   16                        // rows per CTA
#define THREADS 512
#define HPAD    132
#define BPAD    132
#define WSTR    132
#define BQ      (CROWS * BPAD)            // 2112 per k-quarter

// smem layout (float offsets)
#define OFF_W    0                        // Wc[128][WSTR] = 16896
#define OFF_H    16896                    // h[16][HPAD] = 2112
#define OFF_PAR  19008                    // 452
#define OFF_BASE 19460                    // bases[4][16][BPAD] = 8448
#define SMEM_FLOATS (OFF_BASE + 4 * BQ)   // 27908
#define SMEM_BYTES  (SMEM_FLOATS * 4)     // ~109 KB -> 2 CTAs/SM (218 KB)

#define P_CU  0
#define P_CP0 64
#define P_CP1 128
#define P_B1U 192
#define P_B1P 256
#define P_W2U 320
#define P_W2P 384
#define P_B2  448

// HW-tanh GELU (MUFU.TANH): output rel err ~2e-4, passes 1e-3.
__device__ __forceinline__ float gelu_f(float x) {
  float x2 = x * x;
  float t  = fmaf(0.035677408136f, x2, 0.7978845608f);
  float a  = x * t;
  float th;
  asm("tanh.approx.f32 %0, %1;" : "=f"(th) : "f"(a));
  float hx = 0.5f * x;
  return fmaf(hx, th, hx);
}

__device__ __forceinline__ void cp16(uint32_t dst, const void* src) {
  asm volatile("cp.async.cg.shared.global [%0], [%1], 16;" :: "r"(dst), "l"(src));
}
__device__ __forceinline__ void cp4(uint32_t dst, const void* src) {
  asm volatile("cp.async.ca.shared.global [%0], [%1], 4;" :: "r"(dst), "l"(src));
}

extern __shared__ __align__(16) float sm[];

__global__ void __launch_bounds__(THREADS, 2) fem_kernel(
    const float* __restrict__ u,   const float* __restrict__ h,
    const float* __restrict__ W1u, const float* __restrict__ b1u,
    const float* __restrict__ W2u, const float* __restrict__ b2u,
    const float* __restrict__ W1p, const float* __restrict__ b1p,
    const float* __restrict__ W2p, const float* __restrict__ b2p,
    float* __restrict__ out)
{
  const int tid  = threadIdx.x;
  const int lane = tid & 31;
  const int w    = tid >> 5;              // 0..15 == row index in tile
  const int r0   = blockIdx.x * CROWS;
  const uint32_t smb = (uint32_t)__cvta_generic_to_shared(sm);

  // ---- 0) u load first (warp w owns row r0+w): DRAM latency overlaps staging ----
  float4 ua, ub;
  {
    const float4* u4 = reinterpret_cast<const float4*>(u);
    size_t base = (size_t)(r0 + w) * (DIMU / 4);
    ua = u4[base + lane];
    ub = u4[base + 32 + lane];
  }

  // ---- 1) cp.async staging: W repacked to [j][WSTR], params, h tile ----
  {
    const int k  = tid & 127;
    const int j0 = tid >> 7;              // 0..3
    const float* srcU = W1u + (size_t)j0 * 129 + 1 + k;
    const float* srcP = W1p + (size_t)j0 * 130 + 2 + k;
    uint32_t dstU = smb + (uint32_t)(OFF_W + j0 * WSTR + k) * 4;
    uint32_t dstP = smb + (uint32_t)(OFF_W + (HID + j0) * WSTR + k) * 4;
#pragma unroll
    for (int it = 0; it < 16; it++) {     // j = j0 + 4*it covers 0..63
      cp4(dstU, srcU);  srcU += 4 * 129;  dstU += 4 * WSTR * 4;
      cp4(dstP, srcP);  srcP += 4 * 130;  dstP += 4 * WSTR * 4;
    }
  }
  if (tid < HID) {
    uint32_t pb = smb + OFF_PAR * 4;
    cp4(pb + (P_CU  + tid) * 4, W1u + (size_t)tid * 129);
    cp4(pb + (P_CP0 + tid) * 4, W1p + (size_t)tid * 130);
    cp4(pb + (P_CP1 + tid) * 4, W1p + (size_t)tid * 130 + 1);
    cp4(pb + (P_B1U + tid) * 4, b1u + tid);
    cp4(pb + (P_B1P + tid) * 4, b1p + tid);
    cp4(pb + (P_W2U + tid) * 4, W2u + tid);
    cp4(pb + (P_W2P + tid) * 4, W2p + tid);
    if (tid == 0) { cp4(pb + P_B2 * 4, b2u); cp4(pb + (P_B2 + 1) * 4, b2p); }
  }
  {
    const float4* h4 = reinterpret_cast<const float4*>(h) + (size_t)r0 * (DIMH / 4);
    int row = tid >> 5, c4 = tid & 31;    // 512 float4 = exactly 1 per thread
    cp16(smb + (OFF_H + row * HPAD + c4 * 4) * 4, h4 + tid);
  }
  asm volatile("cp.async.commit_group;" ::: "memory");

  // ---- 2) u-counting in registers (covers cp.async drain); counts stay warp-local ----
  float n1f, c01f, c10f, c11f;
  {
    int a0 = ua.x > 0.5f, a1 = ua.y > 0.5f, a2 = ua.z > 0.5f, a3 = ua.w > 0.5f;
    int e0 = ub.x > 0.5f, e1 = ub.y > 0.5f, e2 = ub.z > 0.5f, e3 = ub.w > 0.5f;
    int n1 = a0 + a1 + a2 + a3 + e0 + e1 + e2 + e3;
    const unsigned F = 0xffffffffu;
    int a0n  = __shfl_down_sync(F, a0, 1);
    int e0n  = __shfl_down_sync(F, e0, 1);
    int e0l0 = __shfl_sync(F, e0, 0);
    int c11 = 0, c10 = 0, c01 = 0;
#define ADDP(X, Y) { c11 += (X) & (Y); c10 += (X) & (1 ^ (Y)); c01 += (1 ^ (X)) & (Y); }
    ADDP(a0, a1) ADDP(a1, a2) ADDP(a2, a3)
    int xa = (lane < 31) ? a0n : e0l0;
    ADDP(a3, xa)
    ADDP(e0, e1) ADDP(e1, e2) ADDP(e2, e3)
    if (lane < 31) ADDP(e3, e0n)
#undef ADDP
    n1f  = (float)__reduce_add_sync(F, n1);
    c01f = (float)__reduce_add_sync(F, c01);
    c10f = (float)__reduce_add_sync(F, c10);
    c11f = (float)__reduce_add_sync(F, c11);
  }

  asm volatile("cp.async.wait_group 0;" ::: "memory");
  __syncthreads();

  // ---- 3) GEMM: 16 warps = 4 k-quarters x 4; thread = rows {rb, rb+8} x 8 j ----
  // jg = (w&3)*4 + (lane>>3): warp's 4 jg consecutive, W spacing 132 floats =
  // 4 banks -> conflict-free. j-set = {jg + 16*jj}.
  {
    const int kq = w >> 2;
    const int rb = lane & 7;
    const int jg = ((w & 3) << 2) + (lane >> 3);
    unsigned long long accA[8], accB[8];
#pragma unroll
    for (int jj = 0; jj < 8; jj++) { accA[jj] = 0ull; accB[jj] = 0ull; }
    const float* hA   = sm + OFF_H + rb * HPAD + kq * 32;
    const float* hB   = hA + 8 * HPAD;
    const float* wrow = sm + OFF_W + jg * WSTR + kq * 32;
#pragma unroll 2
    for (int k = 0; k < 32; k += 4) {
      ulonglong2 hvA = *reinterpret_cast<const ulonglong2*>(hA + k);
      ulonglong2 hvB = *reinterpret_cast<const ulonglong2*>(hB + k);
#pragma unroll
      for (int jj = 0; jj < 8; jj++) {
        ulonglong2 wv = *reinterpret_cast<const ulonglong2*>(wrow + jj * 16 * WSTR + k);
        asm("fma.rn.f32x2 %0, %1, %2, %0;" : "+l"(accA[jj]) : "l"(hvA.x), "l"(wv.x));
        asm("fma.rn.f32x2 %0, %1, %2, %0;" : "+l"(accA[jj]) : "l"(hvA.y), "l"(wv.y));
        asm("fma.rn.f32x2 %0, %1, %2, %0;" : "+l"(accB[jj]) : "l"(hvB.x), "l"(wv.x));
        asm("fma.rn.f32x2 %0, %1, %2, %0;" : "+l"(accB[jj]) : "l"(hvB.y), "l"(wv.y));
      }
    }
    // bases[kq][row][j], j = jg + 16*jj: scalar STS, banks 4*rb + jg -> all 32 distinct
    float* dstA = sm + OFF_BASE + kq * BQ + rb * BPAD;
    float* dstB = dstA + 8 * BPAD;
#pragma unroll
    for (int jj = 0; jj < 8; jj++) {
      float lo, hi;
      asm("mov.b64 {%0, %1}, %2;" : "=f"(lo), "=f"(hi) : "l"(accA[jj]));
      dstA[jg + 16 * jj] = lo + hi;
      asm("mov.b64 {%0, %1}, %2;" : "=f"(lo), "=f"(hi) : "l"(accB[jj]));
      dstB[jg + 16 * jj] = lo + hi;
    }
  }
  __syncthreads();

  // ---- 4) epilogue: warp w = row w (counts already in regs, warp-uniform);
  //          lane covers 2 unary + 2 pairwise j -> 12 gelu/thread ----
  {
    const int ju = lane * 2;              // 32 lanes x 2 = 64 j
    const float c00 = 255.0f - c01f - c10f - c11f;
    const float n0  = 256.0f - n1f;
    const float* par = sm + OFF_PAR;
    const float* br  = sm + OFF_BASE + w * BPAD;

    float val = 0.f;
    // unary j = ju, ju+1
    {
      float2 s0 = *reinterpret_cast<const float2*>(br + ju);
      float2 s1 = *reinterpret_cast<const float2*>(br + BQ + ju);
      float2 s2 = *reinterpret_cast<const float2*>(br + 2 * BQ + ju);
      float2 s3 = *reinterpret_cast<const float2*>(br + 3 * BQ + ju);
      float2 bb = *reinterpret_cast<const float2*>(par + P_B1U + ju);
      float2 cu = *reinterpret_cast<const float2*>(par + P_CU  + ju);
      float2 w2 = *reinterpret_cast<const float2*>(par + P_W2U + ju);
      float bs0 = s0.x + s1.x + s2.x + s3.x + bb.x;
      float bs1 = s0.y + s1.y + s2.y + s3.y + bb.y;
      val += w2.x * (n0 * gelu_f(bs0) + n1f * gelu_f(bs0 + cu.x));
      val += w2.y * (n0 * gelu_f(bs1) + n1f * gelu_f(bs1 + cu.y));
    }
    // pairwise j = ju, ju+1 (bases at +64)
    {
      float2 s0 = *reinterpret_cast<const float2*>(br + 64 + ju);
      float2 s1 = *reinterpret_cast<const float2*>(br + BQ + 64 + ju);
      float2 s2 = *reinterpret_cast<const float2*>(br + 2 * BQ + 64 + ju);
      float2 s3 = *reinterpret_cast<const float2*>(br + 3 * BQ + 64 + ju);
      float2 bb = *reinterpret_cast<const float2*>(par + P_B1P + ju);
      float2 A2 = *reinterpret_cast<const float2*>(par + P_CP0 + ju);
      float2 B2 = *reinterpret_cast<const float2*>(par + P_CP1 + ju);
      float2 w2 = *reinterpret_cast<const float2*>(par + P_W2P + ju);
      float bs0 = s0.x + s1.x + s2.x + s3.x + bb.x;
      float bs1 = s0.y + s1.y + s2.y + s3.y + bb.y;
      val += w2.x * (c00 * gelu_f(bs0) + c01f * gelu_f(bs0 + B2.x)
                   + c10f * gelu_f(bs0 + A2.x) + c11f * gelu_f(bs0 + A2.x + B2.x));
      val += w2.y * (c00 * gelu_f(bs1) + c01f * gelu_f(bs1 + B2.y)
                   + c10f * gelu_f(bs1 + A2.y) + c11f * gelu_f(bs1 + A2.y + B2.y));
    }

    const unsigned F = 0xffffffffu;
    val += __shfl_xor_sync(F, val, 1);
    val += __shfl_xor_sync(F, val, 2);
    val += __shfl_xor_sync(F, val, 4);
    val += __shfl_xor_sync(F, val, 8);
    val += __shfl_xor_sync(F, val, 16);
    if (lane == 0)
      out[r0 + w] = val + 256.0f * par[P_B2] + 255.0f * par[P_B2 + 1];
  }
}

extern "C" void kernel_launch(void* const* d_in, const int* in_sizes, int n_in,
                              void* d_out, int out_size) {
  const float* u   = (const float*)d_in[0];
  const float* h   = (const float*)d_in[1];
  const float* W1u = (const float*)d_in[2];
  const float* b1u = (const float*)d_in[3];
  const float* W2u = (const float*)d_in[4];
  const float* b2u = (const float*)d_in[5];
  const float* W1p = (const float*)d_in[6];
  const float* b1p = (const float*)d_in[7];
  const float* W2p = (const float*)d_in[8];
  const float* b2p = (const float*)d_in[9];
  float* out = (float*)d_out;

  int B = in_sizes[1] / DIMH;   // 4096
  cudaFuncSetAttribute(fem_kernel, cudaFuncAttributeMaxDynamicSharedMemorySize, SMEM_BYTES);
  fem_kernel<<<B / CROWS, THREADS, SMEM_BYTES>>>(
      u, h, W1u, b1u, W2u, b2u, W1p, b1p, W2p, b2p, out);
}

// round 16
// speedup vs baseline: 1.2829x; 1.2829x over previous
#include <cuda_runtime.h>
#include <cstdint>
#include <cstddef>

#define HID     64
#define DIMH    128
#define DIMU    256
#define ROWS    32
#define NWARP   16
#define THREADS 512
#define HPAD    132
#define BPAD    132
#define WSTR    132

// smem layout (float offsets)
#define OFF_W    0                        // Wc[128][WSTR] = 16896
#define OFF_H    16896                    // hs[32][132] = 4224
#define OFF_PAR  (OFF_H + ROWS * HPAD)    // 21120 (+452)
#define OFF_CNT  (OFF_PAR + 452)          // 21572: float4[32] (128)
#define OFF_BASE (OFF_CNT + 4 * ROWS)     // 21700: bases[4][32][BPAD]
#define BQ       (ROWS * BPAD)            // 4224 per k-quarter
#define SMEM_FLOATS (OFF_BASE + 4 * BQ)   // 38596
#define SMEM_BYTES  (SMEM_FLOATS * 4)     // ~150.8 KB -> 1 CTA/SM

#define P_CU  0
#define P_CP0 64
#define P_CP1 128
#define P_B1U 192
#define P_B1P 256
#define P_W2U 320
#define P_W2P 384
#define P_B2  448

// HW-tanh GELU (MUFU.TANH): output rel err ~2e-4, passes 1e-3.
__device__ __forceinline__ float gelu_f(float x) {
  float x2 = x * x;
  float t  = fmaf(0.035677408136f, x2, 0.7978845608f);
  float a  = x * t;
  float th;
  asm("tanh.approx.f32 %0, %1;" : "=f"(th) : "f"(a));
  float hx = 0.5f * x;
  return fmaf(hx, th, hx);
}

__device__ __forceinline__ void cp16(uint32_t dst, const void* src) {
  asm volatile("cp.async.cg.shared.global [%0], [%1], 16;" :: "r"(dst), "l"(src));
}
__device__ __forceinline__ void cp4(uint32_t dst, const void* src) {
  asm volatile("cp.async.ca.shared.global [%0], [%1], 4;" :: "r"(dst), "l"(src));
}

extern __shared__ __align__(16) float sm[];

__global__ void __launch_bounds__(THREADS, 1) fem_kernel(
    const float* __restrict__ u,   const float* __restrict__ h,
    const float* __restrict__ W1u, const float* __restrict__ b1u,
    const float* __restrict__ W2u, const float* __restrict__ b2u,
    const float* __restrict__ W1p, const float* __restrict__ b1p,
    const float* __restrict__ W2p, const float* __restrict__ b2p,
    float* __restrict__ out)
{
  const int tid  = threadIdx.x;
  const int lane = tid & 31;
  const int w    = tid >> 5;
  const int r0   = blockIdx.x * ROWS;
  const uint32_t smb = (uint32_t)__cvta_generic_to_shared(sm);

  // ---- 0) u loads first: DRAM latency overlaps staging burst ----
  float4 ua0, ub0, ua1, ub1;
  {
    const float4* u4 = reinterpret_cast<const float4*>(u);
    size_t base0 = (size_t)(r0 + w) * (DIMU / 4);
    size_t base1 = (size_t)(r0 + w + NWARP) * (DIMU / 4);
    ua0 = u4[base0 + lane];
    ub0 = u4[base0 + 32 + lane];
    ua1 = u4[base1 + lane];
    ub1 = u4[base1 + 32 + lane];
  }

  // ---- 1) cp.async staging: W repacked to [j][WSTR] (once), params, h ----
  {
    const int k  = tid & 127;
    const int j0 = tid >> 7;              // 0..3
    const float* srcU = W1u + (size_t)j0 * 129 + 1 + k;
    const float* srcP = W1p + (size_t)j0 * 130 + 2 + k;
    uint32_t dstU = smb + (uint32_t)(OFF_W + j0 * WSTR + k) * 4;
    uint32_t dstP = smb + (uint32_t)(OFF_W + (HID + j0) * WSTR + k) * 4;
#pragma unroll
    for (int it = 0; it < 16; it++) {     // j = j0 + 4*it covers 0..63
      cp4(dstU, srcU);  srcU += 4 * 129;  dstU += 4 * WSTR * 4;
      cp4(dstP, srcP);  srcP += 4 * 130;  dstP += 4 * WSTR * 4;
    }
  }
  if (tid < HID) {
    uint32_t pb = smb + OFF_PAR * 4;
    cp4(pb + (P_CU  + tid) * 4, W1u + (size_t)tid * 129);
    cp4(pb + (P_CP0 + tid) * 4, W1p + (size_t)tid * 130);
    cp4(pb + (P_CP1 + tid) * 4, W1p + (size_t)tid * 130 + 1);
    cp4(pb + (P_B1U + tid) * 4, b1u + tid);
    cp4(pb + (P_B1P + tid) * 4, b1p + tid);
    cp4(pb + (P_W2U + tid) * 4, W2u + tid);
    cp4(pb + (P_W2P + tid) * 4, W2p + tid);
    if (tid == 0) { cp4(pb + P_B2 * 4, b2u); cp4(pb + (P_B2 + 1) * 4, b2p); }
  }
  {
    const float4* h4 = reinterpret_cast<const float4*>(h) + (size_t)r0 * (DIMH / 4);
#pragma unroll
    for (int it = 0; it < 2; it++) {
      int i = tid + it * THREADS;         // 0..1023
      int row = i >> 5, c4 = i & 31;
      cp16(smb + (OFF_H + row * HPAD + c4 * 4) * 4, h4 + i);
    }
  }
  asm volatile("cp.async.commit_group;" ::: "memory");

  // ---- 2) u-counting on registers (covers cp.async drain) ----
  {
#pragma unroll
    for (int t2 = 0; t2 < 2; t2++) {
      int rr = w + t2 * NWARP;
      float4 a = t2 ? ua1 : ua0;
      float4 b = t2 ? ub1 : ub0;
      int a0 = a.x > 0.5f, a1 = a.y > 0.5f, a2 = a.z > 0.5f, a3 = a.w > 0.5f;
      int e0 = b.x > 0.5f, e1 = b.y > 0.5f, e2 = b.z > 0.5f, e3 = b.w > 0.5f;
      int n1 = a0 + a1 + a2 + a3 + e0 + e1 + e2 + e3;
      const unsigned F = 0xffffffffu;
      int a0n  = __shfl_down_sync(F, a0, 1);
      int e0n  = __shfl_down_sync(F, e0, 1);
      int e0l0 = __shfl_sync(F, e0, 0);
      int c11 = 0, c10 = 0, c01 = 0;
#define ADDP(X, Y) { c11 += (X) & (Y); c10 += (X) & (1 ^ (Y)); c01 += (1 ^ (X)) & (Y); }
      ADDP(a0, a1) ADDP(a1, a2) ADDP(a2, a3)
      int xa = (lane < 31) ? a0n : e0l0;
      ADDP(a3, xa)
      ADDP(e0, e1) ADDP(e1, e2) ADDP(e2, e3)
      if (lane < 31) ADDP(e3, e0n)
#undef ADDP
      n1  = __reduce_add_sync(F, n1);
      c11 = __reduce_add_sync(F, c11);
      c10 = __reduce_add_sync(F, c10);
      c01 = __reduce_add_sync(F, c01);
      if (lane == 0)
        *reinterpret_cast<float4*>(sm + OFF_CNT + 4 * rr) =
            make_float4((float)n1, (float)c01, (float)c10, (float)c11);
    }
  }

  asm volatile("cp.async.wait_group 0;" ::: "memory");
  __syncthreads();

  // ---- 3) GEMM: 4 k-quarters x 4 warps; thread = 4 rows x 8 j ----
  // Wide thread tile: per 4-k iter, 12 LDS.128 feed 64 FFMA2 (was 10:32).
  // rows {rb, rb+8, rb+16, rb+24}; jg = (w&3)*4 + (lane>>3); j = jg + 16*jj.
  // Banks: W warp-consecutive jg at 132-float stride -> 4-bank offsets, no
  // conflicts; h 8 distinct rb x 4 banks = 32; bases STS 4*rb+jg distinct.
  {
    const int kq = w >> 2;
    const int rb = lane & 7;
    const int jg = ((w & 3) << 2) + (lane >> 3);
    unsigned long long acc[4][8];
#pragma unroll
    for (int r = 0; r < 4; r++)
#pragma unroll
      for (int jj = 0; jj < 8; jj++) acc[r][jj] = 0ull;
    const float* h0   = sm + OFF_H + rb * HPAD + kq * 32;
    const float* wrow = sm + OFF_W + jg * WSTR + kq * 32;
#pragma unroll
    for (int k = 0; k < 32; k += 4) {
      ulonglong2 hv[4];
#pragma unroll
      for (int r = 0; r < 4; r++)
        hv[r] = *reinterpret_cast<const ulonglong2*>(h0 + r * 8 * HPAD + k);
#pragma unroll
      for (int jj = 0; jj < 8; jj++) {
        ulonglong2 wv = *reinterpret_cast<const ulonglong2*>(wrow + jj * 16 * WSTR + k);
#pragma unroll
        for (int r = 0; r < 4; r++) {
          asm("fma.rn.f32x2 %0, %1, %2, %0;" : "+l"(acc[r][jj]) : "l"(hv[r].x), "l"(wv.x));
          asm("fma.rn.f32x2 %0, %1, %2, %0;" : "+l"(acc[r][jj]) : "l"(hv[r].y), "l"(wv.y));
        }
      }
    }
    // bases[kq][row][j], j = jg + 16*jj
#pragma unroll
    for (int r = 0; r < 4; r++) {
      float* dst = sm + OFF_BASE + kq * BQ + (rb + 8 * r) * BPAD;
#pragma unroll
      for (int jj = 0; jj < 8; jj++) {
        float lo, hi;
        asm("mov.b64 {%0, %1}, %2;" : "=f"(lo), "=f"(hi) : "l"(acc[r][jj]));
        dst[jg + 16 * jj] = lo + hi;
      }
    }
  }
  __syncthreads();

  // ---- 4) balanced branch-free epilogue: every thread 4 unary + 4 pairwise j ----
  {
    const int row = tid >> 4;             // 0..31
    const int tp  = tid & 15;
    const int ju  = tp * 4;

    float4 cnt = *reinterpret_cast<const float4*>(sm + OFF_CNT + 4 * row);
    const float n1 = cnt.x, c01 = cnt.y, c10 = cnt.z, c11 = cnt.w;
    const float c00 = 255.0f - c01 - c10 - c11;
    const float n0 = 256.0f - n1;
    const float* par = sm + OFF_PAR;
    const float* br  = sm + OFF_BASE + row * BPAD;

    float val = 0.f;
    {
      float4 s0 = *reinterpret_cast<const float4*>(br + ju);
      float4 s1 = *reinterpret_cast<const float4*>(br + BQ + ju);
      float4 s2 = *reinterpret_cast<const float4*>(br + 2 * BQ + ju);
      float4 s3 = *reinterpret_cast<const float4*>(br + 3 * BQ + ju);
      float4 bb = *reinterpret_cast<const float4*>(par + P_B1U + ju);
      float4 cu = *reinterpret_cast<const float4*>(par + P_CU  + ju);
      float4 w2 = *reinterpret_cast<const float4*>(par + P_W2U + ju);
      float bs[4] = {s0.x + s1.x + s2.x + s3.x + bb.x,
                     s0.y + s1.y + s2.y + s3.y + bb.y,
                     s0.z + s1.z + s2.z + s3.z + bb.z,
                     s0.w + s1.w + s2.w + s3.w + bb.w};
      float cus[4] = {cu.x, cu.y, cu.z, cu.w};
      float w2s[4] = {w2.x, w2.y, w2.z, w2.w};
#pragma unroll
      for (int i = 0; i < 4; i++)
        val += w2s[i] * (n0 * gelu_f(bs[i]) + n1 * gelu_f(bs[i] + cus[i]));
    }
    {
      float4 s0 = *reinterpret_cast<const float4*>(br + 64 + ju);
      float4 s1 = *reinterpret_cast<const float4*>(br + BQ + 64 + ju);
      float4 s2 = *reinterpret_cast<const float4*>(br + 2 * BQ + 64 + ju);
      float4 s3 = *reinterpret_cast<const float4*>(br + 3 * BQ + 64 + ju);
      float4 bb = *reinterpret_cast<const float4*>(par + P_B1P + ju);
      float4 A4 = *reinterpret_cast<const float4*>(par + P_CP0 + ju);
      float4 B4 = *reinterpret_cast<const float4*>(par + P_CP1 + ju);
      float4 w2 = *reinterpret_cast<const float4*>(par + P_W2P + ju);
      float bs[4] = {s0.x + s1.x + s2.x + s3.x + bb.x,
                     s0.y + s1.y + s2.y + s3.y + bb.y,
                     s0.z + s1.z + s2.z + s3.z + bb.z,
                     s0.w + s1.w + s2.w + s3.w + bb.w};
      float As[4] = {A4.x, A4.y, A4.z, A4.w};
      float Bs[4] = {B4.x, B4.y, B4.z, B4.w};
      float w2s[4] = {w2.x, w2.y, w2.z, w2.w};
#pragma unroll
      for (int i = 0; i < 4; i++)
        val += w2s[i] * (c00 * gelu_f(bs[i])
                       + c01 * gelu_f(bs[i] + Bs[i])
                       + c10 * gelu_f(bs[i] + As[i])
                       + c11 * gelu_f(bs[i] + As[i] + Bs[i]));
    }

    const unsigned F = 0xffffffffu;
    val += __shfl_xor_sync(F, val, 1);
    val += __shfl_xor_sync(F, val, 2);
    val += __shfl_xor_sync(F, val, 4);
    val += __shfl_xor_sync(F, val, 8);
    if (tp == 0)
      out[r0 + row] = val + 256.0f * par[P_B2] + 255.0f * par[P_B2 + 1];
  }
}

extern "C" void kernel_launch(void* const* d_in, const int* in_sizes, int n_in,
                              void* d_out, int out_size) {
  const float* u   = (const float*)d_in[0];
  const float* h   = (const float*)d_in[1];
  const float* W1u = (const float*)d_in[2];
  const float* b1u = (const float*)d_in[3];
  const float* W2u = (const float*)d_in[4];
  const float* b2u = (const float*)d_in[5];
  const float* W1p = (const float*)d_in[6];
  const float* b1p = (const float*)d_in[7];
  const float* W2p = (const float*)d_in[8];
  const float* b2p = (const float*)d_in[9];
  float* out = (float*)d_out;

  int B = in_sizes[1] / DIMH;   // 4096
  cudaFuncSetAttribute(fem_kernel, cudaFuncAttributeMaxDynamicSharedMemorySize, SMEM_BYTES);
  fem_kernel<<<B / ROWS, THREADS, SMEM_BYTES>>>(
      u, h, W1u, b1u, W2u, b2u, W1p, b1p, W2p, b2p, out);
}